// round 5
// baseline (speedup 1.0000x reference)
#include <cuda_runtime.h>
#include <math.h>
#include <cstdint>

#define BSZ  16      // batch
#define NCAP 1152    // primary caps
#define DP   8       // dim primary
#define DDIG 10      // digit caps
#define DD   16      // dim digit

#define TILE_N 16
#define NT (NCAP / TILE_N)   // 72

#define NCH 8                // n-chunks (= cluster size) in k23
#define CHN (NCAP / NCH)     // 144

// Scratch (device globals; fully overwritten every call — no zeroing needed)
__device__ float g_U [BSZ * DDIG * NCAP * DD];   // U_hat [b][d][n][j]
__device__ float g_Tp[BSZ * DDIG * DD * NT];     // partial T [b][d][j][tile]

// -------------------------------------------------------------------------
// K1: votes U_hat[b,d,n,j] = W[d,n,j,:]·u[b,n,:]  +  per-tile partial T
// Grid (DDIG, NT) = 720 CTAs x 256 threads.  (unchanged from passing R3/R4)
// -------------------------------------------------------------------------
__global__ __launch_bounds__(256) void k1_votes(
    const float* __restrict__ u,   // [B][N][DP]
    const float* __restrict__ W)   // [D][N][DD][DP]
{
    const int d    = blockIdx.x;
    const int tile = blockIdx.y;
    const int n0   = tile * TILE_N;
    const int t    = threadIdx.x;
    const int j    = t & 15;
    const int nl   = t >> 4;
    const int n    = n0 + nl;
    const int lane = t & 31;
    const int w    = t >> 5;

    // Issue W DRAM loads FIRST (overlap latency with staging + sync)
    const float4* wp = reinterpret_cast<const float4*>(
        W + ((size_t)(d * NCAP + n) * DD + j) * DP);
    const float4 w0 = wp[0];
    const float4 w1 = wp[1];

    __shared__ __align__(16) float us[BSZ][TILE_N][DP];   // 8 KB
    __shared__ float red[BSZ][8][DD];                     // 8 KB

    // Stage u tile: 512 float4; 2 per thread
    #pragma unroll
    for (int it = 0; it < 2; ++it) {
        const int idx = it * 256 + t;
        const int b   = idx >> 5;       // 32 float4 per b
        const int rem = idx & 31;
        const float4 v = reinterpret_cast<const float4*>(
            u + (size_t)b * NCAP * DP + (size_t)n0 * DP)[rem];
        reinterpret_cast<float4*>(&us[b][0][0])[rem] = v;
    }
    __syncthreads();

    #pragma unroll
    for (int b = 0; b < BSZ; ++b) {
        const float4* up = reinterpret_cast<const float4*>(&us[b][nl][0]);
        const float4 u0 = up[0];
        const float4 u1 = up[1];
        const float acc = w0.x * u0.x + w0.y * u0.y + w0.z * u0.z + w0.w * u0.w
                        + w1.x * u1.x + w1.y * u1.y + w1.z * u1.z + w1.w * u1.w;
        g_U[((size_t)(b * DDIG + d) * NCAP + n) * DD + j] = acc;

        // partial T over nl: warp w holds nl = {2w, 2w+1}; xor16 pairs them
        const float ps = acc + __shfl_xor_sync(0xffffffffu, acc, 16);
        if (lane < 16) red[b][w][lane] = ps;   // lane == j for nl even
    }
    __syncthreads();

    // 256 threads -> (b, j): sum 8 warp partials, store tile partial
    {
        const int b2 = t >> 4;
        const int j2 = t & 15;
        float s = 0.f;
        #pragma unroll
        for (int ww = 0; ww < 8; ++ww) s += red[b2][ww][j2];
        g_Tp[((size_t)(b2 * DDIG + d) * DD + j2) * NT + tile] = s;
    }
}

// -------------------------------------------------------------------------
// K23: fused softmax-weight + combine + squash.
// Grid (NCH, BSZ) with cluster (NCH,1,1): the 8 chunk-CTAs of each b form
// one cluster. 128 threads.
//   pass A: per n in chunk: a[d] = T·U/sqrt8, softmax over d, wgt -> smem
//   pass B: partial S[d][j] over chunk (U re-read, L1-hot)
//   DSMEM: partials pushed to rank 0, cluster barrier, rank 0 squashes.
// -------------------------------------------------------------------------
__global__ __launch_bounds__(128) __cluster_dims__(NCH, 1, 1)
void k23_fused(const float* __restrict__ Bp,   // [D][1][N]
               float* __restrict__ out)        // [B][D][DD]
{
    const int chunk = blockIdx.x;     // == cluster rank
    const int b     = blockIdx.y;
    const int t     = threadIdx.x;

    __shared__ float Tsm[DDIG][DD];            // full T for this b
    __shared__ float wgt_s[DDIG][CHN];         // softmax+prior weights
    __shared__ float red[4][DDIG][DD];         // warp-combine scratch
    __shared__ float Sbuf[NCH][DDIG][DD];      // cluster gather (rank 0 reads)
    __shared__ float Ssm[DDIG][DD];
    __shared__ float coef[DDIG];

    // ---- build T[b,d,j] from 72 tile partials (contiguous, float4) ----
    for (int idx = t; idx < DDIG * DD; idx += 128) {
        const float4* p = reinterpret_cast<const float4*>(
            &g_Tp[(size_t)(b * DDIG * DD + idx) * NT]);
        float s = 0.f;
        #pragma unroll
        for (int k = 0; k < NT / 4; ++k) {
            const float4 v = p[k];
            s += v.x + v.y + v.z + v.w;
        }
        Tsm[idx >> 4][idx & 15] = s;
    }
    __syncthreads();

    const float inv_sqrt8 = 0.3535533905932738f;

    // ---- pass A: softmax weights for this chunk ----
    for (int base = 0; base < CHN; base += 128) {
        const int nl = base + t;
        if (nl < CHN) {
            const int n = chunk * CHN + nl;
            float a[DDIG];
            #pragma unroll
            for (int d = 0; d < DDIG; ++d) {
                const float4* r = reinterpret_cast<const float4*>(
                    g_U + ((size_t)(b * DDIG + d) * NCAP + n) * DD);
                const float4 v0 = r[0], v1 = r[1], v2 = r[2], v3 = r[3];
                const float* T = Tsm[d];
                a[d] = (T[0]  * v0.x + T[1]  * v0.y + T[2]  * v0.z + T[3]  * v0.w
                      + T[4]  * v1.x + T[5]  * v1.y + T[6]  * v1.z + T[7]  * v1.w
                      + T[8]  * v2.x + T[9]  * v2.y + T[10] * v2.z + T[11] * v2.w
                      + T[12] * v3.x + T[13] * v3.y + T[14] * v3.z + T[15] * v3.w)
                      * inv_sqrt8;
            }
            float m = a[0];
            #pragma unroll
            for (int d = 1; d < DDIG; ++d) m = fmaxf(m, a[d]);
            float e[DDIG], denom = 0.f;
            #pragma unroll
            for (int d = 0; d < DDIG; ++d) { e[d] = __expf(a[d] - m); denom += e[d]; }
            const float rden = 1.f / denom;
            #pragma unroll
            for (int d = 0; d < DDIG; ++d) {
                wgt_s[d][nl] = e[d] * rden + __ldg(&Bp[(size_t)d * NCAP + n]);
            }
        }
    }
    __syncthreads();

    // ---- pass B: partial S over this chunk; threads = (16 j) x (8 sub) ----
    const int j    = t & 15;
    const int sub  = t >> 4;
    const int lane = t & 31;
    const int w    = t >> 5;

    float acc[DDIG];
    #pragma unroll
    for (int d = 0; d < DDIG; ++d) {
        const float* Ud = g_U + ((size_t)(b * DDIG + d) * NCAP + chunk * CHN) * DD + j;
        float s = 0.f;
        #pragma unroll 6
        for (int k = 0; k < CHN / 8; ++k) {     // 18 iters
            const int nl = k * 8 + sub;
            s += wgt_s[d][nl] * Ud[(size_t)nl * DD];
        }
        acc[d] = s;
    }

    // reduce over sub: xor16 pairs sub within warp, then 4-warp smem combine
    #pragma unroll
    for (int d = 0; d < DDIG; ++d)
        acc[d] += __shfl_xor_sync(0xffffffffu, acc[d], 16);
    if (lane < 16) {
        #pragma unroll
        for (int d = 0; d < DDIG; ++d) red[w][d][lane] = acc[d];
    }
    __syncthreads();

    // combine 4 warps and push this CTA's partial S to rank 0's Sbuf[chunk]
    for (int idx = t; idx < DDIG * DD; idx += 128) {
        const int d  = idx >> 4;
        const int jj = idx & 15;
        const float v = red[0][d][jj] + red[1][d][jj] + red[2][d][jj] + red[3][d][jj];
        uint32_t laddr = (uint32_t)__cvta_generic_to_shared(&Sbuf[chunk][d][jj]);
        uint32_t raddr;
        asm volatile("mapa.shared::cluster.u32 %0, %1, 0;" : "=r"(raddr) : "r"(laddr));
        asm volatile("st.shared::cluster.f32 [%0], %1;" :: "r"(raddr), "f"(v) : "memory");
    }

    // cluster barrier: release makes the DSMEM stores visible to rank 0
    asm volatile("barrier.cluster.arrive.aligned;" ::: "memory");
    asm volatile("barrier.cluster.wait.aligned;" ::: "memory");

    // ---- rank 0: final sum + squash + write ----
    if (chunk == 0) {
        for (int idx = t; idx < DDIG * DD; idx += 128) {
            const int d  = idx >> 4;
            const int jj = idx & 15;
            float s = 0.f;
            #pragma unroll
            for (int r = 0; r < NCH; ++r) s += Sbuf[r][d][jj];
            Ssm[d][jj] = s;
        }
        __syncthreads();
        if (t < DDIG) {
            float nn = 0.f;
            #pragma unroll
            for (int jj = 0; jj < DD; ++jj) nn += Ssm[t][jj] * Ssm[t][jj];
            const float norm = sqrtf(nn);
            const float EPS  = 1e-7f;
            coef[t] = (1.f - 1.f / (__expf(norm) + EPS)) / (norm + EPS);
        }
        __syncthreads();
        for (int idx = t; idx < DDIG * DD; idx += 128) {
            out[(size_t)b * DDIG * DD + idx] = coef[idx >> 4] * Ssm[idx >> 4][idx & 15];
        }
    }
}

// -------------------------------------------------------------------------
extern "C" void kernel_launch(void* const* d_in, const int* in_sizes, int n_in,
                              void* d_out, int out_size)
{
    const float* u  = (const float*)d_in[0];   // primary_caps [16,1152,8]
    const float* W  = (const float*)d_in[1];   // W            [10,1152,16,8]
    const float* Bp = (const float*)d_in[2];   // B_prior      [10,1,1152]
    float* out      = (float*)d_out;           // [16,10,16]

    (void)in_sizes; (void)n_in; (void)out_size;

    k1_votes <<<dim3(DDIG, NT), 256>>>(u, W);
    k23_fused<<<dim3(NCH, BSZ), 128>>>(Bp, out);
}

// round 6
// speedup vs baseline: 1.3425x; 1.3425x over previous
#include <cuda_runtime.h>
#include <math.h>
#include <cstdint>

#define BSZ  16      // batch
#define NCAP 1152    // primary caps
#define DP   8       // dim primary
#define DDIG 10      // digit caps
#define DD   16      // dim digit

#define TILE_N 16
#define NT (NCAP / TILE_N)   // 72

#define NCH 9                // n-chunks per batch in k2
#define CHN (NCAP / NCH)     // 128

// Scratch (device globals; no allocation allowed)
__device__ float g_U [BSZ * DDIG * NCAP * DD];   // U_hat [b][d][n][j]
__device__ float g_Tp[BSZ * DDIG * DD * NT];     // partial T [b][d][j][tile]
__device__ float g_Sp[BSZ * NCH * DDIG * DD];    // partial S [b][chunk][d][j]
__device__ unsigned int g_cnt[BSZ];              // zero-init; self-resetting

// -------------------------------------------------------------------------
// K1: votes U_hat[b,d,n,j] = W[d,n,j,:]·u[b,n,:]  +  per-tile partial T
// Grid (DDIG, NT) = 720 CTAs x 256 threads.  (proven in R3/R4)
// -------------------------------------------------------------------------
__global__ __launch_bounds__(256) void k1_votes(
    const float* __restrict__ u,   // [B][N][DP]
    const float* __restrict__ W)   // [D][N][DD][DP]
{
    const int d    = blockIdx.x;
    const int tile = blockIdx.y;
    const int n0   = tile * TILE_N;
    const int t    = threadIdx.x;
    const int j    = t & 15;
    const int nl   = t >> 4;
    const int n    = n0 + nl;
    const int lane = t & 31;
    const int w    = t >> 5;

    // Issue W DRAM loads FIRST (overlap latency with staging + sync)
    const float4* wp = reinterpret_cast<const float4*>(
        W + ((size_t)(d * NCAP + n) * DD + j) * DP);
    const float4 w0 = wp[0];
    const float4 w1 = wp[1];

    __shared__ __align__(16) float us[BSZ][TILE_N][DP];   // 8 KB
    __shared__ float red[BSZ][8][DD];                     // 8 KB

    #pragma unroll
    for (int it = 0; it < 2; ++it) {
        const int idx = it * 256 + t;
        const int b   = idx >> 5;       // 32 float4 per b
        const int rem = idx & 31;
        const float4 v = reinterpret_cast<const float4*>(
            u + (size_t)b * NCAP * DP + (size_t)n0 * DP)[rem];
        reinterpret_cast<float4*>(&us[b][0][0])[rem] = v;
    }
    __syncthreads();

    #pragma unroll
    for (int b = 0; b < BSZ; ++b) {
        const float4* up = reinterpret_cast<const float4*>(&us[b][nl][0]);
        const float4 u0 = up[0];
        const float4 u1 = up[1];
        const float acc = w0.x * u0.x + w0.y * u0.y + w0.z * u0.z + w0.w * u0.w
                        + w1.x * u1.x + w1.y * u1.y + w1.z * u1.z + w1.w * u1.w;
        g_U[((size_t)(b * DDIG + d) * NCAP + n) * DD + j] = acc;

        const float ps = acc + __shfl_xor_sync(0xffffffffu, acc, 16);
        if (lane < 16) red[b][w][lane] = ps;
    }
    __syncthreads();

    {
        const int b2 = t >> 4;
        const int j2 = t & 15;
        float s = 0.f;
        #pragma unroll
        for (int ww = 0; ww < 8; ++ww) s += red[b2][ww][j2];
        g_Tp[((size_t)(b2 * DDIG + d) * DD + j2) * NT + tile] = s;
    }
}

// -------------------------------------------------------------------------
// K2: softmax weights + partial S + (last CTA per b) finalize + squash.
// Grid (BSZ, NCH) = 144 CTAs x 128 threads. No clusters.
// -------------------------------------------------------------------------
__global__ __launch_bounds__(128) void k2_rest(
    const float* __restrict__ Bp,   // [D][1][N]
    float* __restrict__ out)        // [B][D][DD]
{
    const int b     = blockIdx.x;
    const int chunk = blockIdx.y;
    const int t     = threadIdx.x;

    __shared__ float Tsm[DDIG][DD];
    __shared__ float wgt_s[DDIG][CHN];     // 5 KB
    __shared__ float red[4][DDIG][DD];
    __shared__ float Ssm[DDIG][DD];
    __shared__ float coef[DDIG];

    // ---- build T[b,d,j] from 72 contiguous tile partials ----
    for (int idx = t; idx < DDIG * DD; idx += 128) {
        const float4* p = reinterpret_cast<const float4*>(
            &g_Tp[(size_t)(b * DDIG * DD + idx) * NT]);
        float s = 0.f;
        #pragma unroll
        for (int k = 0; k < NT / 4; ++k) {
            const float4 v = p[k];
            s += v.x + v.y + v.z + v.w;
        }
        Tsm[idx >> 4][idx & 15] = s;
    }
    __syncthreads();

    const float inv_sqrt8 = 0.3535533905932738f;

    // ---- pass A: softmax weights; one n per thread (CHN == 128) ----
    {
        const int nl = t;
        const int n  = chunk * CHN + nl;
        float a[DDIG];
        #pragma unroll
        for (int d = 0; d < DDIG; ++d) {
            const float4* r = reinterpret_cast<const float4*>(
                g_U + ((size_t)(b * DDIG + d) * NCAP + n) * DD);
            const float4 v0 = r[0], v1 = r[1], v2 = r[2], v3 = r[3];
            const float* T = Tsm[d];
            a[d] = (T[0]  * v0.x + T[1]  * v0.y + T[2]  * v0.z + T[3]  * v0.w
                  + T[4]  * v1.x + T[5]  * v1.y + T[6]  * v1.z + T[7]  * v1.w
                  + T[8]  * v2.x + T[9]  * v2.y + T[10] * v2.z + T[11] * v2.w
                  + T[12] * v3.x + T[13] * v3.y + T[14] * v3.z + T[15] * v3.w)
                  * inv_sqrt8;
        }
        float m = a[0];
        #pragma unroll
        for (int d = 1; d < DDIG; ++d) m = fmaxf(m, a[d]);
        float e[DDIG], denom = 0.f;
        #pragma unroll
        for (int d = 0; d < DDIG; ++d) { e[d] = __expf(a[d] - m); denom += e[d]; }
        const float rden = 1.f / denom;
        #pragma unroll
        for (int d = 0; d < DDIG; ++d) {
            wgt_s[d][nl] = e[d] * rden + __ldg(&Bp[(size_t)d * NCAP + n]);
        }
    }
    __syncthreads();

    // ---- pass B: partial S over chunk; threads = (16 j) x (8 sub); U L1-hot ----
    const int j    = t & 15;
    const int sub  = t >> 4;
    const int lane = t & 31;
    const int w    = t >> 5;

    float acc[DDIG];
    #pragma unroll
    for (int d = 0; d < DDIG; ++d) {
        const float* Ud = g_U + ((size_t)(b * DDIG + d) * NCAP + chunk * CHN) * DD + j;
        float s = 0.f;
        #pragma unroll 4
        for (int k = 0; k < CHN / 8; ++k) {      // 16 iters
            const int nl = k * 8 + sub;
            s += wgt_s[d][nl] * Ud[(size_t)nl * DD];
        }
        acc[d] = s;
    }

    #pragma unroll
    for (int d = 0; d < DDIG; ++d)
        acc[d] += __shfl_xor_sync(0xffffffffu, acc[d], 16);
    if (lane < 16) {
        #pragma unroll
        for (int d = 0; d < DDIG; ++d) red[w][d][lane] = acc[d];
    }
    __syncthreads();

    // write this CTA's partial S to gmem
    float* Sp = g_Sp + (size_t)(b * NCH + chunk) * DDIG * DD;
    for (int idx = t; idx < DDIG * DD; idx += 128) {
        const int d  = idx >> 4;
        const int jj = idx & 15;
        Sp[idx] = red[0][d][jj] + red[1][d][jj] + red[2][d][jj] + red[3][d][jj];
    }

    // ---- last-CTA-per-b finalize (threadFenceReduction pattern) ----
    __threadfence();
    __shared__ unsigned int is_last;
    __syncthreads();                 // all partial stores issued before fence+atomic
    if (t == 0) {
        // wraps: old==NCH-1 -> 0, so counter self-resets for the next call
        is_last = (atomicInc(&g_cnt[b], NCH - 1) == NCH - 1) ? 1u : 0u;
    }
    __syncthreads();
    if (!is_last) return;

    for (int idx = t; idx < DDIG * DD; idx += 128) {
        float s = 0.f;
        const float* base = g_Sp + (size_t)b * NCH * DDIG * DD + idx;
        #pragma unroll
        for (int c = 0; c < NCH; ++c)
            s += __ldcg(base + (size_t)c * DDIG * DD);   // L1-bypass: fresh data
        Ssm[idx >> 4][idx & 15] = s;
    }
    __syncthreads();
    if (t < DDIG) {
        float nn = 0.f;
        #pragma unroll
        for (int jj = 0; jj < DD; ++jj) nn += Ssm[t][jj] * Ssm[t][jj];
        const float norm = sqrtf(nn);
        const float EPS  = 1e-7f;
        coef[t] = (1.f - 1.f / (__expf(norm) + EPS)) / (norm + EPS);
    }
    __syncthreads();
    for (int idx = t; idx < DDIG * DD; idx += 128) {
        out[(size_t)b * DDIG * DD + idx] = coef[idx >> 4] * Ssm[idx >> 4][idx & 15];
    }
}

// -------------------------------------------------------------------------
extern "C" void kernel_launch(void* const* d_in, const int* in_sizes, int n_in,
                              void* d_out, int out_size)
{
    const float* u  = (const float*)d_in[0];   // primary_caps [16,1152,8]
    const float* W  = (const float*)d_in[1];   // W            [10,1152,16,8]
    const float* Bp = (const float*)d_in[2];   // B_prior      [10,1,1152]
    float* out      = (float*)d_out;           // [16,10,16]

    (void)in_sizes; (void)n_in; (void)out_size;

    k1_votes<<<dim3(DDIG, NT), 256>>>(u, W);
    k2_rest <<<dim3(BSZ, NCH), 128>>>(Bp, out);
}

// round 7
// speedup vs baseline: 1.6267x; 1.2117x over previous
#include <cuda_runtime.h>
#include <math.h>
#include <cstdint>

#define BSZ  16      // batch
#define NCAP 1152    // primary caps
#define DP   8       // dim primary
#define DDIG 10      // digit caps
#define DD   16      // dim digit

#define TILE_N 16
#define NT (NCAP / TILE_N)   // 72

#define NCH 36               // n-chunks per batch in k2
#define CHN (NCAP / NCH)     // 32

// Scratch (device globals; zero-initialized at load; invariants restored per call)
__device__ float g_U [BSZ * DDIG * NCAP * DD];   // U_hat [b][d][n][j]
__device__ float g_T [BSZ * DDIG * DD];          // T[b][d][j] (atomic-accumulated, re-zeroed)
__device__ float g_Sp[BSZ * NCH * DDIG * DD];    // partial S [b][chunk][d][j]
__device__ unsigned int g_cnt[BSZ];              // self-resetting wrap counter

// -------------------------------------------------------------------------
// K1: votes U_hat[b,d,n,j] = W[d,n,j,:]·u[b,n,:]  +  atomic T accumulation
// Grid (DDIG, NT) = 720 CTAs x 256 threads.
// -------------------------------------------------------------------------
__global__ __launch_bounds__(256) void k1_votes(
    const float* __restrict__ u,   // [B][N][DP]
    const float* __restrict__ W)   // [D][N][DD][DP]
{
    const int d    = blockIdx.x;
    const int tile = blockIdx.y;
    const int n0   = tile * TILE_N;
    const int t    = threadIdx.x;
    const int j    = t & 15;
    const int nl   = t >> 4;
    const int n    = n0 + nl;
    const int lane = t & 31;
    const int w    = t >> 5;

    // Issue W DRAM loads FIRST (overlap latency with staging + sync)
    const float4* wp = reinterpret_cast<const float4*>(
        W + ((size_t)(d * NCAP + n) * DD + j) * DP);
    const float4 w0 = wp[0];
    const float4 w1 = wp[1];

    __shared__ __align__(16) float us[BSZ][TILE_N][DP];   // 8 KB
    __shared__ float red[BSZ][8][DD];                     // 8 KB

    #pragma unroll
    for (int it = 0; it < 2; ++it) {
        const int idx = it * 256 + t;
        const int b   = idx >> 5;       // 32 float4 per b
        const int rem = idx & 31;
        const float4 v = reinterpret_cast<const float4*>(
            u + (size_t)b * NCAP * DP + (size_t)n0 * DP)[rem];
        reinterpret_cast<float4*>(&us[b][0][0])[rem] = v;
    }
    __syncthreads();

    #pragma unroll
    for (int b = 0; b < BSZ; ++b) {
        const float4* up = reinterpret_cast<const float4*>(&us[b][nl][0]);
        const float4 u0 = up[0];
        const float4 u1 = up[1];
        const float acc = w0.x * u0.x + w0.y * u0.y + w0.z * u0.z + w0.w * u0.w
                        + w1.x * u1.x + w1.y * u1.y + w1.z * u1.z + w1.w * u1.w;
        g_U[((size_t)(b * DDIG + d) * NCAP + n) * DD + j] = acc;

        const float ps = acc + __shfl_xor_sync(0xffffffffu, acc, 16);
        if (lane < 16) red[b][w][lane] = ps;
    }
    __syncthreads();

    {
        const int b2 = t >> 4;
        const int j2 = t & 15;
        float s = 0.f;
        #pragma unroll
        for (int ww = 0; ww < 8; ++ww) s += red[b2][ww][j2];
        atomicAdd(&g_T[(b2 * DDIG + d) * DD + j2], s);   // 72 adds per address
    }
}

// -------------------------------------------------------------------------
// K2: softmax weights + partial S + (last CTA per b) finalize + squash.
// Grid (BSZ, NCH) = 576 CTAs x 128 threads.
//   pass A: 32 n x 4 dsub threads -> dots with MLP~12, smem exchange,
//           t<32 does softmax over d.
//   pass B: (16 j x 8 sub), d innermost -> 10 independent loads / iter.
// -------------------------------------------------------------------------
__global__ __launch_bounds__(128) void k2_rest(
    const float* __restrict__ Bp,   // [D][1][N]
    float* __restrict__ out)        // [B][D][DD]
{
    const int b     = blockIdx.x;
    const int chunk = blockIdx.y;
    const int t     = threadIdx.x;
    const int nbase = chunk * CHN;

    __shared__ float Tsm[DDIG][DD];        // 640 B
    __shared__ float a_s[CHN][DDIG + 2];   // pad vs bank conflicts
    __shared__ float wgt_s[DDIG][CHN];
    __shared__ float red[4][DDIG][DD];
    __shared__ float Ssm[DDIG][DD];
    __shared__ float coef[DDIG];

    // ---- T: one 160-float read (atomically accumulated by k1) ----
    for (int idx = t; idx < DDIG * DD; idx += 128)
        Tsm[idx >> 4][idx & 15] = g_T[b * DDIG * DD + idx];
    __syncthreads();

    const float inv_sqrt8 = 0.3535533905932738f;

    // ---- pass A: dots. thread = (n_local, q); q covers d = q, q+4, q+8 ----
    {
        const int nl = t >> 2;
        const int q  = t & 3;
        const int n  = nbase + nl;
        #pragma unroll
        for (int dq = 0; dq < 3; ++dq) {
            const int d = q + dq * 4;
            if (d < DDIG) {
                const float4* r = reinterpret_cast<const float4*>(
                    g_U + ((size_t)(b * DDIG + d) * NCAP + n) * DD);
                const float4 v0 = r[0], v1 = r[1], v2 = r[2], v3 = r[3];
                const float* T = Tsm[d];
                a_s[nl][d] =
                    (T[0]  * v0.x + T[1]  * v0.y + T[2]  * v0.z + T[3]  * v0.w
                   + T[4]  * v1.x + T[5]  * v1.y + T[6]  * v1.z + T[7]  * v1.w
                   + T[8]  * v2.x + T[9]  * v2.y + T[10] * v2.z + T[11] * v2.w
                   + T[12] * v3.x + T[13] * v3.y + T[14] * v3.z + T[15] * v3.w)
                   * inv_sqrt8;
            }
        }
    }
    __syncthreads();

    // ---- softmax over d (one thread per n) ----
    if (t < CHN) {
        const int nl = t;
        const int n  = nbase + nl;
        float a[DDIG];
        #pragma unroll
        for (int d = 0; d < DDIG; ++d) a[d] = a_s[nl][d];
        float m = a[0];
        #pragma unroll
        for (int d = 1; d < DDIG; ++d) m = fmaxf(m, a[d]);
        float e[DDIG], denom = 0.f;
        #pragma unroll
        for (int d = 0; d < DDIG; ++d) { e[d] = __expf(a[d] - m); denom += e[d]; }
        const float rden = 1.f / denom;
        #pragma unroll
        for (int d = 0; d < DDIG; ++d)
            wgt_s[d][nl] = e[d] * rden + __ldg(&Bp[(size_t)d * NCAP + n]);
    }
    __syncthreads();

    // ---- pass B: partial S; threads (16 j x 8 sub); d innermost (MLP 10) ----
    const int j    = t & 15;
    const int sub  = t >> 4;
    const int lane = t & 31;
    const int w    = t >> 5;

    float acc[DDIG];
    #pragma unroll
    for (int d = 0; d < DDIG; ++d) acc[d] = 0.f;

    #pragma unroll
    for (int k = 0; k < CHN / 8; ++k) {        // 4 iters
        const int nl = k * 8 + sub;
        const size_t noff = (size_t)(nbase + nl) * DD + j;
        #pragma unroll
        for (int d = 0; d < DDIG; ++d) {
            acc[d] += wgt_s[d][nl] *
                      g_U[((size_t)(b * DDIG + d) * NCAP) * DD + noff];
        }
    }

    #pragma unroll
    for (int d = 0; d < DDIG; ++d)
        acc[d] += __shfl_xor_sync(0xffffffffu, acc[d], 16);
    if (lane < 16) {
        #pragma unroll
        for (int d = 0; d < DDIG; ++d) red[w][d][lane] = acc[d];
    }
    __syncthreads();

    // write this CTA's partial S
    float* Sp = g_Sp + (size_t)(b * NCH + chunk) * DDIG * DD;
    for (int idx = t; idx < DDIG * DD; idx += 128) {
        const int d  = idx >> 4;
        const int jj = idx & 15;
        Sp[idx] = red[0][d][jj] + red[1][d][jj] + red[2][d][jj] + red[3][d][jj];
    }

    // ---- last-CTA-per-b finalize (threadFenceReduction pattern) ----
    __threadfence();
    __shared__ unsigned int is_last;
    __syncthreads();
    if (t == 0)
        is_last = (atomicInc(&g_cnt[b], NCH - 1) == NCH - 1) ? 1u : 0u;
    __syncthreads();
    if (!is_last) return;

    // all 36 CTAs of this b have read g_T and written partials: reset T for
    // the next kernel_launch call, then reduce + squash.
    for (int idx = t; idx < DDIG * DD; idx += 128)
        g_T[b * DDIG * DD + idx] = 0.f;

    for (int idx = t; idx < DDIG * DD; idx += 128) {
        float s = 0.f;
        const float* base = g_Sp + (size_t)b * NCH * DDIG * DD + idx;
        #pragma unroll
        for (int c = 0; c < NCH; ++c)
            s += __ldcg(base + (size_t)c * DDIG * DD);   // L1-bypass: fresh data
        Ssm[idx >> 4][idx & 15] = s;
    }
    __syncthreads();
    if (t < DDIG) {
        float nn = 0.f;
        #pragma unroll
        for (int jj = 0; jj < DD; ++jj) nn += Ssm[t][jj] * Ssm[t][jj];
        const float norm = sqrtf(nn);
        const float EPS  = 1e-7f;
        coef[t] = (1.f - 1.f / (__expf(norm) + EPS)) / (norm + EPS);
    }
    __syncthreads();
    for (int idx = t; idx < DDIG * DD; idx += 128)
        out[(size_t)b * DDIG * DD + idx] = coef[idx >> 4] * Ssm[idx >> 4][idx & 15];
}

// -------------------------------------------------------------------------
extern "C" void kernel_launch(void* const* d_in, const int* in_sizes, int n_in,
                              void* d_out, int out_size)
{
    const float* u  = (const float*)d_in[0];   // primary_caps [16,1152,8]
    const float* W  = (const float*)d_in[1];   // W            [10,1152,16,8]
    const float* Bp = (const float*)d_in[2];   // B_prior      [10,1,1152]
    float* out      = (float*)d_out;           // [16,10,16]

    (void)in_sizes; (void)n_in; (void)out_size;

    k1_votes<<<dim3(DDIG, NT), 256>>>(u, W);
    k2_rest <<<dim3(BSZ, NCH), 128>>>(Bp, out);
}

// round 8
// speedup vs baseline: 1.6459x; 1.0118x over previous
#include <cuda_runtime.h>
#include <math.h>
#include <cstdint>

#define BSZ  16      // batch
#define NCAP 1152    // primary caps
#define DP   8       // dim primary
#define DDIG 10      // digit caps
#define DD   16      // dim digit

#define TILE_N 16
#define NT (NCAP / TILE_N)   // 72

#define NCH 18               // n-chunks per batch in k2
#define CHN (NCAP / NCH)     // 64

// Scratch (device globals; zero-init at load; invariants restored every call)
__device__ float g_U [BSZ * DDIG * NCAP * DD];   // U_hat [b][d][n][j]
__device__ float g_T [BSZ * DDIG * DD];          // T (k1 atomics; re-zeroed by k2)
__device__ float g_S [BSZ * DDIG * DD];          // S accumulator (k2 REDG; re-zeroed)
__device__ unsigned int g_cnt[BSZ];              // self-resetting wrap counter

// -------------------------------------------------------------------------
// K1: votes U_hat[b,d,n,j] = W[d,n,j,:]·u[b,n,:]  +  atomic T accumulation
// Grid (DDIG, NT) = 720 CTAs x 256 threads.   (proven R7)
// -------------------------------------------------------------------------
__global__ __launch_bounds__(256) void k1_votes(
    const float* __restrict__ u,   // [B][N][DP]
    const float* __restrict__ W)   // [D][N][DD][DP]
{
    const int d    = blockIdx.x;
    const int tile = blockIdx.y;
    const int n0   = tile * TILE_N;
    const int t    = threadIdx.x;
    const int j    = t & 15;
    const int nl   = t >> 4;
    const int n    = n0 + nl;
    const int lane = t & 31;
    const int w    = t >> 5;

    const float4* wp = reinterpret_cast<const float4*>(
        W + ((size_t)(d * NCAP + n) * DD + j) * DP);
    const float4 w0 = wp[0];
    const float4 w1 = wp[1];

    __shared__ __align__(16) float us[BSZ][TILE_N][DP];   // 8 KB
    __shared__ float red[BSZ][8][DD];                     // 8 KB

    #pragma unroll
    for (int it = 0; it < 2; ++it) {
        const int idx = it * 256 + t;
        const int b   = idx >> 5;
        const int rem = idx & 31;
        const float4 v = reinterpret_cast<const float4*>(
            u + (size_t)b * NCAP * DP + (size_t)n0 * DP)[rem];
        reinterpret_cast<float4*>(&us[b][0][0])[rem] = v;
    }
    __syncthreads();

    #pragma unroll
    for (int b = 0; b < BSZ; ++b) {
        const float4* up = reinterpret_cast<const float4*>(&us[b][nl][0]);
        const float4 u0 = up[0];
        const float4 u1 = up[1];
        const float acc = w0.x * u0.x + w0.y * u0.y + w0.z * u0.z + w0.w * u0.w
                        + w1.x * u1.x + w1.y * u1.y + w1.z * u1.z + w1.w * u1.w;
        g_U[((size_t)(b * DDIG + d) * NCAP + n) * DD + j] = acc;

        const float ps = acc + __shfl_xor_sync(0xffffffffu, acc, 16);
        if (lane < 16) red[b][w][lane] = ps;
    }
    __syncthreads();

    {
        const int b2 = t >> 4;
        const int j2 = t & 15;
        float s = 0.f;
        #pragma unroll
        for (int ww = 0; ww < 8; ++ww) s += red[b2][ww][j2];
        atomicAdd(&g_T[(b2 * DDIG + d) * DD + j2], s);
    }
}

// -------------------------------------------------------------------------
// K2: SMEM-tiled: load U tile once (compute T-dots in flight), softmax,
//     combine from SMEM, REDG partial S into g_S, last-CTA finalize+squash.
// Grid (BSZ, NCH) = 288 CTAs x 256 threads.
// -------------------------------------------------------------------------
__global__ __launch_bounds__(256) void k2_rest(
    const float* __restrict__ Bp,   // [D][1][N]
    float* __restrict__ out)        // [B][D][DD]
{
    const int b     = blockIdx.x;
    const int chunk = blockIdx.y;
    const int t     = threadIdx.x;
    const int nbase = chunk * CHN;

    __shared__ float Tsm[DDIG][DD];                       // 640 B
    __shared__ __align__(16) float Us[DDIG][CHN][DD];     // 40 KB
    __shared__ float a_s[CHN][12];                        // 3 KB (pad)
    __shared__ float wgt_s[DDIG][CHN];                    // 2.5 KB
    __shared__ float Ssm[DDIG][DD];
    __shared__ float coef[DDIG];
    __shared__ unsigned int is_last;

    if (t < DDIG * DD) Tsm[t >> 4][t & 15] = g_T[b * DDIG * DD + t];
    __syncthreads();

    const float inv_sqrt8 = 0.3535533905932738f;

    // ---- load phase: rows r = d*CHN + nl (640 rows); 2-3 rows/thread,
    //      all loads issued up-front (MLP 8-12); T-dot computed in flight ----
    {
        auto rowp = [&](int r) {
            const int d  = r >> 6;          // CHN == 64
            const int nl = r & 63;
            return reinterpret_cast<const float4*>(
                g_U + ((size_t)(b * DDIG + d) * NCAP + nbase + nl) * DD);
        };
        auto proc = [&](int r, const float4* A) {
            const int d  = r >> 6;
            const int nl = r & 63;
            float4* s = reinterpret_cast<float4*>(&Us[d][nl][0]);
            s[0] = A[0]; s[1] = A[1]; s[2] = A[2]; s[3] = A[3];
            const float* T = Tsm[d];
            a_s[nl][d] =
                (T[0]  * A[0].x + T[1]  * A[0].y + T[2]  * A[0].z + T[3]  * A[0].w
               + T[4]  * A[1].x + T[5]  * A[1].y + T[6]  * A[1].z + T[7]  * A[1].w
               + T[8]  * A[2].x + T[9]  * A[2].y + T[10] * A[2].z + T[11] * A[2].w
               + T[12] * A[3].x + T[13] * A[3].y + T[14] * A[3].z + T[15] * A[3].w)
               * inv_sqrt8;
        };

        const int r0 = t, r1 = t + 256, r2 = t + 512;
        const bool has2 = (r2 < DDIG * CHN);
        float4 A0[4], A1[4], A2[4];
        const float4* p0 = rowp(r0);
        const float4* p1 = rowp(r1);
        #pragma unroll
        for (int i = 0; i < 4; ++i) A0[i] = p0[i];
        #pragma unroll
        for (int i = 0; i < 4; ++i) A1[i] = p1[i];
        if (has2) {
            const float4* p2 = rowp(r2);
            #pragma unroll
            for (int i = 0; i < 4; ++i) A2[i] = p2[i];
        }
        proc(r0, A0);
        proc(r1, A1);
        if (has2) proc(r2, A2);
    }
    __syncthreads();

    // ---- softmax over d (one thread per n) ----
    if (t < CHN) {
        const int nl = t;
        const int n  = nbase + nl;
        float a[DDIG];
        #pragma unroll
        for (int d = 0; d < DDIG; ++d) a[d] = a_s[nl][d];
        float m = a[0];
        #pragma unroll
        for (int d = 1; d < DDIG; ++d) m = fmaxf(m, a[d]);
        float e[DDIG], denom = 0.f;
        #pragma unroll
        for (int d = 0; d < DDIG; ++d) { e[d] = __expf(a[d] - m); denom += e[d]; }
        const float rden = 1.f / denom;
        #pragma unroll
        for (int d = 0; d < DDIG; ++d)
            wgt_s[d][nl] = e[d] * rden + __ldg(&Bp[(size_t)d * NCAP + n]);
    }
    __syncthreads();

    // ---- combine from SMEM: threads (16 j x 16 sub); d innermost ----
    {
        const int j    = t & 15;
        const int sub  = t >> 4;
        const int lane = t & 31;

        float acc[DDIG];
        #pragma unroll
        for (int d = 0; d < DDIG; ++d) acc[d] = 0.f;

        #pragma unroll
        for (int k = 0; k < CHN / 16; ++k) {     // 4 iters
            const int nl = k * 16 + sub;
            #pragma unroll
            for (int d = 0; d < DDIG; ++d)
                acc[d] += wgt_s[d][nl] * Us[d][nl][j];
        }

        #pragma unroll
        for (int d = 0; d < DDIG; ++d)
            acc[d] += __shfl_xor_sync(0xffffffffu, acc[d], 16);

        if (lane < 16) {     // lane == j here
            #pragma unroll
            for (int d = 0; d < DDIG; ++d)
                atomicAdd(&g_S[(b * DDIG + d) * DD + lane], acc[d]);
        }
    }

    // ---- last-CTA-per-b finalize ----
    __threadfence();
    __syncthreads();
    if (t == 0)
        is_last = (atomicInc(&g_cnt[b], NCH - 1) == NCH - 1) ? 1u : 0u;
    __syncthreads();
    if (!is_last) return;

    if (t < DDIG * DD) {
        const float sv = __ldcg(&g_S[b * DDIG * DD + t]);   // L2-fresh
        Ssm[t >> 4][t & 15] = sv;
        g_S[b * DDIG * DD + t] = 0.f;    // restore invariant for next call
        g_T[b * DDIG * DD + t] = 0.f;
    }
    __syncthreads();
    if (t < DDIG) {
        float nn = 0.f;
        #pragma unroll
        for (int jj = 0; jj < DD; ++jj) nn += Ssm[t][jj] * Ssm[t][jj];
        const float norm = sqrtf(nn);
        const float EPS  = 1e-7f;
        coef[t] = (1.f - 1.f / (__expf(norm) + EPS)) / (norm + EPS);
    }
    __syncthreads();
    if (t < DDIG * DD)
        out[(size_t)b * DDIG * DD + t] = coef[t >> 4] * Ssm[t >> 4][t & 15];
}

// -------------------------------------------------------------------------
extern "C" void kernel_launch(void* const* d_in, const int* in_sizes, int n_in,
                              void* d_out, int out_size)
{
    const float* u  = (const float*)d_in[0];   // primary_caps [16,1152,8]
    const float* W  = (const float*)d_in[1];   // W            [10,1152,16,8]
    const float* Bp = (const float*)d_in[2];   // B_prior      [10,1,1152]
    float* out      = (float*)d_out;           // [16,10,16]

    (void)in_sizes; (void)n_in; (void)out_size;

    k1_votes<<<dim3(DDIG, NT), 256>>>(u, W);
    k2_rest <<<dim3(BSZ, NCH), 256>>>(Bp, out);
}